// round 10
// baseline (speedup 1.0000x reference)
#include <cuda_runtime.h>
#include <cuda_bf16.h>
#include <math.h>

// Problem constants: NC=1000, K=8, N=32, D=128  -> G = 8000 groups
#define G_TOT 8000
#define NPT   32
#define DIM   128
#define ITERS 20
#define TOLF  1e-6f
#define EPSF  1e-7f
#define CLIPF 1e-7f

// Static scratch (no runtime allocation)
__device__ float g_vnorm[(size_t)ITERS * G_TOT];
__device__ float g_lossT[(size_t)(ITERS + 1) * G_TOT];
__device__ float g_maxv[ITERS];

using u64 = unsigned long long;

// ---- packed f32x2 helpers ----
__device__ __forceinline__ u64 pk2(float a, float b) {
    u64 r; asm("mov.b64 %0, {%1,%2};" : "=l"(r) : "f"(a), "f"(b)); return r;
}
__device__ __forceinline__ float2 upk2(u64 v) {
    float2 r; asm("mov.b64 {%0,%1}, %2;" : "=f"(r.x), "=f"(r.y) : "l"(v)); return r;
}
__device__ __forceinline__ u64 ffma2(u64 a, u64 b, u64 c) {
    u64 d; asm("fma.rn.f32x2 %0, %1, %2, %3;" : "=l"(d) : "l"(a), "l"(b), "l"(c)); return d;
}
__device__ __forceinline__ u64 fadd2(u64 a, u64 b) {
    u64 d; asm("add.rn.f32x2 %0, %1, %2;" : "=l"(d) : "l"(a), "l"(b)); return d;
}

__device__ __forceinline__ float warpSum(float v) {
    #pragma unroll
    for (int o = 16; o > 0; o >>= 1)
        v += __shfl_xor_sync(0xffffffffu, v, o);
    return v;
}
// packed pairwise warp sum (two reductions in one butterfly)
__device__ __forceinline__ u64 warpSum2(u64 v) {
    #pragma unroll
    for (int o = 16; o > 0; o >>= 1)
        v = fadd2(v, __shfl_xor_sync(0xffffffffu, v, o));
    return v;
}

// ---------------------------------------------------------------------------
// Gram-space Karcher kernel. One warp per group.
//
// mu_t = s * sum_m alpha_m x^_m  stays in span(X^); all iterations run on
// 32-dim coefficients. Lane n owns: Gram row Ghat[n][0..31] (32 regs),
// alpha_n, d_n = (Ghat·alpha)_n, plus per-point scalars (lane = point n).
// Per iteration the ONLY matvec is Ghat·w; d is maintained by the exp-map
// recurrence d' = (cos·s)·d + k·e with e = Ghat·beta derived from Ghat·w.
// X lives only in smem (16.9KB); registers ~90 -> 13 warps/SM.
// ---------------------------------------------------------------------------
__global__ void __launch_bounds__(32) karcher_kernel(const float* __restrict__ X) {
    __shared__ float4 Xs4[NPT * 33];   // 32 rows x 33 float4 (pitch 33 => conflict-free strided)

    const int g    = blockIdx.x;
    const int lane = threadIdx.x;
    const float4* __restrict__ Xg = (const float4*)X + (size_t)g * (NPT * DIM / 4);

    // Stage X tile (coalesced LDG.128; same-row lanes -> conflict-free STS)
    #pragma unroll
    for (int i = lane; i < NPT * DIM / 4; i += 32) {
        int n = i >> 5, j = i & 31;
        Xs4[n * 33 + j] = Xg[i];
    }
    __syncwarp();

    // ---- Raw Gram row: gr[m] = <x_lane, x_m>. Dependency-free FFMA2 stream.
    float gr[NPT];
    #pragma unroll
    for (int m = 0; m < NPT; m++) gr[m] = 0.f;

    #pragma unroll 1
    for (int c = 0; c < 4; c++) {              // 4 chunks of 32 dims
        float4 xn[8];
        #pragma unroll
        for (int k = 0; k < 8; k++)            // lane-strided, conflict-free (pitch 33)
            xn[k] = Xs4[lane * 33 + c * 8 + k];
        #pragma unroll
        for (int m = 0; m < NPT; m++) {
            u64 acc = 0ull;
            #pragma unroll
            for (int k = 0; k < 8; k++) {
                float4 xm = Xs4[m * 33 + c * 8 + k];   // broadcast LDS.128
                acc = ffma2(pk2(xn[k].x, xn[k].y), pk2(xm.x, xm.y), acc);
                acc = ffma2(pk2(xn[k].z, xn[k].w), pk2(xm.z, xm.w), acc);
            }
            float2 a = upk2(acc);
            gr[m] += a.x + a.y;
        }
    }

    // ---- Normalize: Ghat = D^-1/2 G D^-1/2  (diag = ||x_lane||^2)
    float diag = 0.f;
    #pragma unroll
    for (int m = 0; m < NPT; m++) diag = (lane == m) ? gr[m] : diag;
    float inv = rsqrtf(fmaxf(diag, 1e-24f));   // == 1/max(||x||,1e-12)
    #pragma unroll
    for (int m = 0; m < NPT; m++) {
        float invm = __shfl_sync(0xffffffffu, inv, m);
        gr[m] *= inv * invm;
    }

    // ---- Init: alpha = 1 (mu0 dir = sum x^), d = Ghat·1 = row sum
    float alpha = 1.f, d;
    {
        float a0 = 0, a1 = 0, a2 = 0, a3 = 0;
        #pragma unroll
        for (int m = 0; m < NPT; m += 4) {
            a0 += gr[m]; a1 += gr[m + 1]; a2 += gr[m + 2]; a3 += gr[m + 3];
        }
        d = (a0 + a1) + (a2 + a3);
    }
    float s = rsqrtf(fmaxf(warpSum(alpha * d), 1e-24f));   // 1/||m^||

    const float I32 = 1.0f / 32.0f;

    #pragma unroll 1
    for (int it = 0; it < ITERS; ++it) {
        // lane = point: dot with current mu
        float dot   = s * d;
        float dc    = fminf(fmaxf(dot, -1.0f + CLIPF), 1.0f - CLIPF);
        float theta = acosf(dc);
        float st    = fmaxf(sqrtf(fmaf(-dc, dc, 1.0f)), EPSF);  // sin(acos(dc))
        float w     = __fdividef(theta, st);

        // matvec gw = (Ghat·w)_lane  (32 shfl + 32 FFMA, 4 accumulators)
        float a0 = 0, a1 = 0, a2 = 0, a3 = 0;
        #pragma unroll
        for (int m = 0; m < NPT; m += 4) {
            a0 = fmaf(gr[m],     __shfl_sync(0xffffffffu, w, m),     a0);
            a1 = fmaf(gr[m + 1], __shfl_sync(0xffffffffu, w, m + 1), a1);
            a2 = fmaf(gr[m + 2], __shfl_sync(0xffffffffu, w, m + 2), a2);
            a3 = fmaf(gr[m + 3], __shfl_sync(0xffffffffu, w, m + 3), a3);
        }
        float gw = (a0 + a1) + (a2 + a3);

        // c = sum w*dot (unclipped dot) and loss = sum theta^2, one butterfly
        u64 pr = warpSum2(pk2(w * dot, theta * theta));
        float2 cl = upk2(pr);
        if (lane == 0) g_lossT[(size_t)it * G_TOT + g] = cl.y;

        // v coeffs: beta = w/32 - (c*s/32)*alpha ;  e = Ghat·beta
        float cs   = cl.x * s * I32;
        float beta = fmaf(-cs, alpha, w * I32);
        float e    = fmaf(-cs, d,     gw * I32);

        // ||v||^2 = beta^T Ghat beta
        float vq    = warpSum(beta * e);
        float vnorm = fmaxf(sqrtf(fmaxf(vq, 0.0f)), EPSF);
        if (lane == 0) g_vnorm[(size_t)it * G_TOT + g] = vnorm;

        // exp map: alpha' = (cos·s)·alpha + (sin/a)·beta ; d' follows linearly
        float ca  = __cosf(vnorm);
        float k   = __fdividef(__sinf(vnorm), vnorm);
        float cas = ca * s;
        alpha = fmaf(cas, alpha, k * beta);
        d     = fmaf(cas, d,     k * e);

        // deferred renormalization: ||m^'||^2 = alpha'^T Ghat alpha' = sum a'*d'
        s = rsqrtf(fmaxf(warpSum(alpha * d), 1e-24f));
    }

    // ---- loss candidate t = 20 (never frozen): dots = s*d already maintained
    float dc = fminf(fmaxf(s * d, -1.0f + CLIPF), 1.0f - CLIPF);
    float th = acosf(dc);
    float ls = warpSum(th * th);
    if (lane == 0) g_lossT[(size_t)ITERS * G_TOT + g] = ls;
}

// ---------------------------------------------------------------------------
// Kernel 2: per-iteration max over groups of vnorm
// ---------------------------------------------------------------------------
__global__ void max_kernel() {
    __shared__ float sh[256];
    const int it = blockIdx.x;
    float m = 0.f;
    for (int i = threadIdx.x; i < G_TOT; i += 256)
        m = fmaxf(m, g_vnorm[(size_t)it * G_TOT + i]);
    sh[threadIdx.x] = m;
    __syncthreads();
    for (int s = 128; s > 0; s >>= 1) {
        if (threadIdx.x < s) sh[threadIdx.x] = fmaxf(sh[threadIdx.x], sh[threadIdx.x + s]);
        __syncthreads();
    }
    if (threadIdx.x == 0) g_maxv[it] = sh[0];
}

// ---------------------------------------------------------------------------
// Kernel 3: t* selection + deterministic mean of the selected losses
// ---------------------------------------------------------------------------
__global__ void final_kernel(float* __restrict__ out) {
    __shared__ float sh[1024];
    __shared__ int ts;
    if (threadIdx.x == 0) {
        int t = ITERS;
        for (int i = 0; i < ITERS; i++)
            if (g_maxv[i] < TOLF) { t = i; break; }
        ts = t;
    }
    __syncthreads();
    const int t = ts;
    float acc = 0.f;
    for (int i = threadIdx.x; i < G_TOT; i += 1024)
        acc += g_lossT[(size_t)t * G_TOT + i];
    sh[threadIdx.x] = acc;
    __syncthreads();
    for (int s = 512; s > 0; s >>= 1) {
        if (threadIdx.x < s) sh[threadIdx.x] += sh[threadIdx.x + s];
        __syncthreads();
    }
    if (threadIdx.x == 0) out[0] = sh[0] * (1.0f / (float)G_TOT);
}

// ---------------------------------------------------------------------------
extern "C" void kernel_launch(void* const* d_in, const int* in_sizes, int n_in,
                              void* d_out, int out_size) {
    const float* X = (const float*)d_in[0];
    float* out = (float*)d_out;

    karcher_kernel<<<G_TOT, 32>>>(X);
    max_kernel<<<ITERS, 256>>>();
    final_kernel<<<1, 1024>>>(out);
}

// round 11
// speedup vs baseline: 1.0870x; 1.0870x over previous
#include <cuda_runtime.h>
#include <cuda_bf16.h>
#include <math.h>

// Problem constants: NC=1000, K=8, N=32, D=128  -> G = 8000 groups
#define G_TOT 8000
#define NPT   32
#define DIM   128
#define ITERS 20
#define TOLF  1e-6f
#define EPSF  1e-7f
#define CLIPF 1e-7f

#define PN 34        // u64 pitch for k-pair-major chunk buffer (even -> 16B-aligned rows)
#define CT 33        // float pitch for Ct redistribution buffer (conflict-free row reads)

// Static scratch (no runtime allocation)
__device__ float g_vnorm[(size_t)ITERS * G_TOT];
__device__ float g_lossT[(size_t)(ITERS + 1) * G_TOT];
__device__ float g_maxv[ITERS];

using u64 = unsigned long long;

// ---- packed f32x2 helpers ----
__device__ __forceinline__ u64 pk2(float a, float b) {
    u64 r; asm("mov.b64 %0, {%1,%2};" : "=l"(r) : "f"(a), "f"(b)); return r;
}
__device__ __forceinline__ float2 upk2(u64 v) {
    float2 r; asm("mov.b64 {%0,%1}, %2;" : "=f"(r.x), "=f"(r.y) : "l"(v)); return r;
}
__device__ __forceinline__ u64 ffma2(u64 a, u64 b, u64 c) {
    u64 d; asm("fma.rn.f32x2 %0, %1, %2, %3;" : "=l"(d) : "l"(a), "l"(b), "l"(c)); return d;
}
__device__ __forceinline__ u64 fadd2(u64 a, u64 b) {
    u64 d; asm("add.rn.f32x2 %0, %1, %2;" : "=l"(d) : "l"(a), "l"(b)); return d;
}

__device__ __forceinline__ float warpSum(float v) {
    #pragma unroll
    for (int o = 16; o > 0; o >>= 1)
        v += __shfl_xor_sync(0xffffffffu, v, o);
    return v;
}
// packed pairwise warp sum (two reductions in one butterfly)
__device__ __forceinline__ u64 warpSum2(u64 v) {
    #pragma unroll
    for (int o = 16; o > 0; o >>= 1)
        v = fadd2(v, __shfl_xor_sync(0xffffffffu, v, o));
    return v;
}

// ---------------------------------------------------------------------------
// Gram-space Karcher kernel, v2. One warp per group.
//
// Phase 1 (build): G = X·Xt via register-tiled outer products. X streamed in
// 4 k-chunks of 32 dims, stored k-pair-major as packed f32x2 (u64) so each
// k-pair step is 6 vector LDS + 32 FFMA2 into a 4x8 per-lane micro-tile
// (lane = (row-block lr = lane>>2, col-block lc = lane&3)).
// Phase 2: normalize to Ghat = D^-1/2 G D^-1/2, redistribute row-per-lane
// through smem. Phase 3: 32-dim coefficient iteration (validated in R10).
// ---------------------------------------------------------------------------
__global__ void __launch_bounds__(32, 16) karcher_kernel(const float* __restrict__ X) {
    __shared__ u64   Xc2[16 * PN];      // one 32-dim chunk, k-pair-major, packed
    __shared__ float Ct[NPT * CT];      // Gram redistribution buffer
    __shared__ float dsh[NPT];          // diagonal (||x_n||^2)
    __shared__ float ish[NPT];          // inv norms

    const int g    = blockIdx.x;
    const int lane = threadIdx.x;
    const int lr   = lane >> 2;         // row-block: rows 4lr..4lr+3
    const int lc   = lane & 3;          // col-block: cols 8lc..8lc+7
    const float4* __restrict__ Xg = (const float4*)X + (size_t)g * (NPT * DIM / 4);

    u64 acc[4][8];
    #pragma unroll
    for (int i = 0; i < 4; i++)
        #pragma unroll
        for (int j = 0; j < 8; j++) acc[i][j] = 0ull;

    // ---- Phase 1: streamed Gram build
    #pragma unroll 1
    for (int c = 0; c < 4; c++) {
        // Load chunk c: X[p][32c..32c+31] for all points p. Coalesced LDG.128.
        #pragma unroll
        for (int t = 0; t < 8; t++) {
            int p = 4 * t + (lane >> 3);
            int j = lane & 7;
            float4 v = Xg[p * 32 + c * 8 + j];
            Xc2[(2 * j)     * PN + p] = pk2(v.x, v.y);
            Xc2[(2 * j + 1) * PN + p] = pk2(v.z, v.w);
        }
        __syncwarp();

        #pragma unroll
        for (int k2 = 0; k2 < 16; k2++) {
            const u64* base = &Xc2[k2 * PN];
            u64 ar[4], bc[8];
            #pragma unroll
            for (int i = 0; i < 4; i++) ar[i] = base[4 * lr + i];
            #pragma unroll
            for (int j = 0; j < 8; j++) bc[j] = base[8 * lc + j];
            #pragma unroll
            for (int i = 0; i < 4; i++)
                #pragma unroll
                for (int j = 0; j < 8; j++)
                    acc[i][j] = ffma2(ar[i], bc[j], acc[i][j]);
        }
        __syncwarp();
    }

    // Reduce packed accumulators to scalars C[i][j]
    float C[4][8];
    #pragma unroll
    for (int i = 0; i < 4; i++)
        #pragma unroll
        for (int j = 0; j < 8; j++) {
            float2 a = upk2(acc[i][j]);
            C[i][j] = a.x + a.y;
        }

    // ---- Phase 2: normalize + redistribute
    // Diagonal entries: row r = 4lr+i is in this lane's cols iff (r>>3)==lc
    #pragma unroll
    for (int i = 0; i < 4; i++) {
        int r = 4 * lr + i;
        if ((r >> 3) == lc) dsh[r] = C[i][r - 8 * lc];
    }
    __syncwarp();
    ish[lane] = rsqrtf(fmaxf(dsh[lane], 1e-24f));   // == 1/max(||x||,1e-12)
    __syncwarp();

    float ir[4], ic[8];
    #pragma unroll
    for (int i = 0; i < 4; i++) ir[i] = ish[4 * lr + i];
    #pragma unroll
    for (int j = 0; j < 8; j++) ic[j] = ish[8 * lc + j];
    #pragma unroll
    for (int i = 0; i < 4; i++)
        #pragma unroll
        for (int j = 0; j < 8; j++)
            Ct[(4 * lr + i) * CT + 8 * lc + j] = C[i][j] * ir[i] * ic[j];
    __syncwarp();

    // Row-per-lane Gram row (conflict-free: (33*lane + m) % 32 all-distinct)
    float gr[NPT];
    #pragma unroll
    for (int m = 0; m < NPT; m++) gr[m] = Ct[lane * CT + m];

    // ---- Phase 3: coefficient-space iteration (same as validated R10)
    float alpha = 1.f, d;
    {
        float a0 = 0, a1 = 0, a2 = 0, a3 = 0;
        #pragma unroll
        for (int m = 0; m < NPT; m += 4) {
            a0 += gr[m]; a1 += gr[m + 1]; a2 += gr[m + 2]; a3 += gr[m + 3];
        }
        d = (a0 + a1) + (a2 + a3);
    }
    float s = rsqrtf(fmaxf(warpSum(alpha * d), 1e-24f));   // 1/||m^||

    const float I32 = 1.0f / 32.0f;

    #pragma unroll 1
    for (int it = 0; it < ITERS; ++it) {
        float dot   = s * d;
        float dc    = fminf(fmaxf(dot, -1.0f + CLIPF), 1.0f - CLIPF);
        float theta = acosf(dc);
        float st    = fmaxf(sqrtf(fmaf(-dc, dc, 1.0f)), EPSF);  // sin(acos(dc))
        float w     = __fdividef(theta, st);

        // gw = (Ghat·w)_lane
        float a0 = 0, a1 = 0, a2 = 0, a3 = 0;
        #pragma unroll
        for (int m = 0; m < NPT; m += 4) {
            a0 = fmaf(gr[m],     __shfl_sync(0xffffffffu, w, m),     a0);
            a1 = fmaf(gr[m + 1], __shfl_sync(0xffffffffu, w, m + 1), a1);
            a2 = fmaf(gr[m + 2], __shfl_sync(0xffffffffu, w, m + 2), a2);
            a3 = fmaf(gr[m + 3], __shfl_sync(0xffffffffu, w, m + 3), a3);
        }
        float gw = (a0 + a1) + (a2 + a3);

        // c = sum w*dot (unclipped) and loss = sum theta^2, one butterfly
        u64 pr = warpSum2(pk2(w * dot, theta * theta));
        float2 cl = upk2(pr);
        if (lane == 0) g_lossT[(size_t)it * G_TOT + g] = cl.y;

        // v coeffs: beta = w/32 - (c*s/32)*alpha ; e = Ghat·beta
        float cs   = cl.x * s * I32;
        float beta = fmaf(-cs, alpha, w * I32);
        float e    = fmaf(-cs, d,     gw * I32);

        float vq    = warpSum(beta * e);               // ||v||^2
        float vnorm = fmaxf(sqrtf(fmaxf(vq, 0.0f)), EPSF);
        if (lane == 0) g_vnorm[(size_t)it * G_TOT + g] = vnorm;

        // exp map + deferred renormalization
        float ca  = __cosf(vnorm);
        float k   = __fdividef(__sinf(vnorm), vnorm);
        float cas = ca * s;
        alpha = fmaf(cas, alpha, k * beta);
        d     = fmaf(cas, d,     k * e);
        s = rsqrtf(fmaxf(warpSum(alpha * d), 1e-24f));
    }

    // loss candidate t = 20 (never frozen)
    float dc = fminf(fmaxf(s * d, -1.0f + CLIPF), 1.0f - CLIPF);
    float th = acosf(dc);
    float ls = warpSum(th * th);
    if (lane == 0) g_lossT[(size_t)ITERS * G_TOT + g] = ls;
}

// ---------------------------------------------------------------------------
// Kernel 2: per-iteration max over groups of vnorm
// ---------------------------------------------------------------------------
__global__ void max_kernel() {
    __shared__ float sh[256];
    const int it = blockIdx.x;
    float m = 0.f;
    for (int i = threadIdx.x; i < G_TOT; i += 256)
        m = fmaxf(m, g_vnorm[(size_t)it * G_TOT + i]);
    sh[threadIdx.x] = m;
    __syncthreads();
    for (int s = 128; s > 0; s >>= 1) {
        if (threadIdx.x < s) sh[threadIdx.x] = fmaxf(sh[threadIdx.x], sh[threadIdx.x + s]);
        __syncthreads();
    }
    if (threadIdx.x == 0) g_maxv[it] = sh[0];
}

// ---------------------------------------------------------------------------
// Kernel 3: t* selection + deterministic mean of the selected losses
// ---------------------------------------------------------------------------
__global__ void final_kernel(float* __restrict__ out) {
    __shared__ float sh[1024];
    __shared__ int ts;
    if (threadIdx.x == 0) {
        int t = ITERS;
        for (int i = 0; i < ITERS; i++)
            if (g_maxv[i] < TOLF) { t = i; break; }
        ts = t;
    }
    __syncthreads();
    const int t = ts;
    float acc = 0.f;
    for (int i = threadIdx.x; i < G_TOT; i += 1024)
        acc += g_lossT[(size_t)t * G_TOT + i];
    sh[threadIdx.x] = acc;
    __syncthreads();
    for (int s = 512; s > 0; s >>= 1) {
        if (threadIdx.x < s) sh[threadIdx.x] += sh[threadIdx.x + s];
        __syncthreads();
    }
    if (threadIdx.x == 0) out[0] = sh[0] * (1.0f / (float)G_TOT);
}

// ---------------------------------------------------------------------------
extern "C" void kernel_launch(void* const* d_in, const int* in_sizes, int n_in,
                              void* d_out, int out_size) {
    const float* X = (const float*)d_in[0];
    float* out = (float*)d_out;

    karcher_kernel<<<G_TOT, 32>>>(X);
    max_kernel<<<ITERS, 256>>>();
    final_kernel<<<1, 1024>>>(out);
}

// round 13
// speedup vs baseline: 1.1245x; 1.0344x over previous
#include <cuda_runtime.h>
#include <cuda_bf16.h>
#include <math.h>

// Problem constants: NC=1000, K=8, N=32, D=128  -> G = 8000 groups
#define G_TOT 8000
#define NPT   32
#define DIM   128
#define ITERS 20
#define TOLF  1e-6f
#define EPSF  1e-7f
#define CLIPF 1e-7f

#define PN 34        // u64 pitch for k-pair-major chunk buffer
#define CT 33        // float pitch for Ct redistribution buffer

// Static scratch (no runtime allocation)
__device__ float g_vnorm[(size_t)ITERS * G_TOT];
__device__ float g_lossT[(size_t)(ITERS + 1) * G_TOT];
__device__ float g_maxv[ITERS];

using u64 = unsigned long long;

// ---- packed f32x2 helpers ----
__device__ __forceinline__ u64 pk2(float a, float b) {
    u64 r; asm("mov.b64 %0, {%1,%2};" : "=l"(r) : "f"(a), "f"(b)); return r;
}
__device__ __forceinline__ float2 upk2(u64 v) {
    float2 r; asm("mov.b64 {%0,%1}, %2;" : "=f"(r.x), "=f"(r.y) : "l"(v)); return r;
}
__device__ __forceinline__ u64 ffma2(u64 a, u64 b, u64 c) {
    u64 d; asm("fma.rn.f32x2 %0, %1, %2, %3;" : "=l"(d) : "l"(a), "l"(b), "l"(c)); return d;
}
__device__ __forceinline__ u64 fadd2(u64 a, u64 b) {
    u64 d; asm("add.rn.f32x2 %0, %1, %2;" : "=l"(d) : "l"(a), "l"(b)); return d;
}

__device__ __forceinline__ float warpSum(float v) {
    #pragma unroll
    for (int o = 16; o > 0; o >>= 1)
        v += __shfl_xor_sync(0xffffffffu, v, o);
    return v;
}

// ---------------------------------------------------------------------------
// Gram-space Karcher kernel, v3: ONE butterfly per iteration.
// State per lane n: Gram row gr[0..31], d_n = (Ghat·alpha)_n. Warp scalars:
// t = alpha^T Ghat alpha, s = rsqrt(t). Exp map is affine in (d, t):
//   d' = P d + Q gw,  t' = P^2 t + 2PQ S1 + Q^2 S3
// with S1 = sum w*d, S3 = sum w*gw from a single packed 3-wide butterfly.
// vnorm^2 = (S3 - S1^2/t)/1024. alpha is never materialized.
// ---------------------------------------------------------------------------
__global__ void __launch_bounds__(32, 16) karcher_kernel(const float* __restrict__ X) {
    __shared__ u64   Xc2[16 * PN];      // one 32-dim chunk, k-pair-major, packed
    __shared__ float Ct[NPT * CT];      // Gram redistribution buffer
    __shared__ float dsh[NPT];          // diagonal (||x_n||^2)
    __shared__ float ish[NPT];          // inv norms

    const int g    = blockIdx.x;
    const int lane = threadIdx.x;
    const int lr   = lane >> 2;         // row-block: rows 4lr..4lr+3
    const int lc   = lane & 3;          // col-block: cols 8lc..8lc+7
    const float4* __restrict__ Xg = (const float4*)X + (size_t)g * (NPT * DIM / 4);

    u64 acc[4][8];
    #pragma unroll
    for (int i = 0; i < 4; i++)
        #pragma unroll
        for (int j = 0; j < 8; j++) acc[i][j] = 0ull;

    // ---- Phase 1: streamed register-tiled Gram build (validated R11)
    #pragma unroll 1
    for (int c = 0; c < 4; c++) {
        #pragma unroll
        for (int t = 0; t < 8; t++) {
            int p = 4 * t + (lane >> 3);
            int j = lane & 7;
            float4 v = Xg[p * 32 + c * 8 + j];
            Xc2[(2 * j)     * PN + p] = pk2(v.x, v.y);
            Xc2[(2 * j + 1) * PN + p] = pk2(v.z, v.w);
        }
        __syncwarp();

        #pragma unroll
        for (int k2 = 0; k2 < 16; k2++) {
            const u64* base = &Xc2[k2 * PN];
            u64 ar[4], bc[8];
            #pragma unroll
            for (int i = 0; i < 4; i++) ar[i] = base[4 * lr + i];
            #pragma unroll
            for (int j = 0; j < 8; j++) bc[j] = base[8 * lc + j];
            #pragma unroll
            for (int i = 0; i < 4; i++)
                #pragma unroll
                for (int j = 0; j < 8; j++)
                    acc[i][j] = ffma2(ar[i], bc[j], acc[i][j]);
        }
        __syncwarp();
    }

    float C[4][8];
    #pragma unroll
    for (int i = 0; i < 4; i++)
        #pragma unroll
        for (int j = 0; j < 8; j++) {
            float2 a = upk2(acc[i][j]);
            C[i][j] = a.x + a.y;
        }

    // ---- Phase 2: normalize + redistribute row-per-lane
    #pragma unroll
    for (int i = 0; i < 4; i++) {
        int r = 4 * lr + i;
        if ((r >> 3) == lc) dsh[r] = C[i][r - 8 * lc];
    }
    __syncwarp();
    ish[lane] = rsqrtf(fmaxf(dsh[lane], 1e-24f));   // == 1/max(||x||,1e-12)
    __syncwarp();

    float ir[4], ic[8];
    #pragma unroll
    for (int i = 0; i < 4; i++) ir[i] = ish[4 * lr + i];
    #pragma unroll
    for (int j = 0; j < 8; j++) ic[j] = ish[8 * lc + j];
    #pragma unroll
    for (int i = 0; i < 4; i++)
        #pragma unroll
        for (int j = 0; j < 8; j++)
            Ct[(4 * lr + i) * CT + 8 * lc + j] = C[i][j] * ir[i] * ic[j];
    __syncwarp();

    float gr[NPT];
    #pragma unroll
    for (int m = 0; m < NPT; m++) gr[m] = Ct[lane * CT + m];   // conflict-free

    // ---- Phase 3: iteration with single butterfly
    // init: alpha = 1 -> d = row sum, t = sum d
    float d;
    {
        float a0 = 0, a1 = 0, a2 = 0, a3 = 0;
        #pragma unroll
        for (int m = 0; m < NPT; m += 4) {
            a0 += gr[m]; a1 += gr[m + 1]; a2 += gr[m + 2]; a3 += gr[m + 3];
        }
        d = (a0 + a1) + (a2 + a3);
    }
    float t = fmaxf(warpSum(d), 1e-24f);    // alpha^T Ghat alpha
    float s = rsqrtf(t);                    // 1/||m^||

    const float I32   = 1.0f / 32.0f;
    const float I1024 = 1.0f / 1024.0f;

    #pragma unroll 1
    for (int it = 0; it < ITERS; ++it) {
        float dot   = s * d;
        float dc    = fminf(fmaxf(dot, -1.0f + CLIPF), 1.0f - CLIPF);
        float theta = acosf(dc);
        float st    = fmaxf(sqrtf(fmaf(-dc, dc, 1.0f)), EPSF);  // sin(acos(dc))
        float w     = __fdividef(theta, st);

        // gw = (Ghat·w)_lane  (32 broadcast shfl + 32 FFMA, 4 accumulators)
        float a0 = 0, a1 = 0, a2 = 0, a3 = 0;
        #pragma unroll
        for (int m = 0; m < NPT; m += 4) {
            a0 = fmaf(gr[m],     __shfl_sync(0xffffffffu, w, m),     a0);
            a1 = fmaf(gr[m + 1], __shfl_sync(0xffffffffu, w, m + 1), a1);
            a2 = fmaf(gr[m + 2], __shfl_sync(0xffffffffu, w, m + 2), a2);
            a3 = fmaf(gr[m + 3], __shfl_sync(0xffffffffu, w, m + 3), a3);
        }
        float gw = (a0 + a1) + (a2 + a3);

        // ---- ONE 3-wide butterfly: S1 = sum w*d, S2 = sum theta^2, S3 = sum w*gw
        u64   p1 = pk2(w * d, theta * theta);
        float p2 = w * gw;
        #pragma unroll
        for (int o = 16; o > 0; o >>= 1) {
            p1 = fadd2(p1, __shfl_xor_sync(0xffffffffu, p1, o));
            p2 +=          __shfl_xor_sync(0xffffffffu, p2, o);
        }
        float2 s12 = upk2(p1);
        float S1 = s12.x, S2 = s12.y, S3 = p2;
        if (lane == 0) g_lossT[(size_t)it * G_TOT + g] = S2;

        // ||v||^2 = (S3 - S1^2/t) / 1024   (c = s*S1, cs = c*s/32 = S1*s^2/32)
        float vq    = fmaxf((S3 - S1 * S1 * __fdividef(1.0f, t)) * I1024, 0.0f);
        float vnorm = fmaxf(sqrtf(vq), EPSF);
        if (lane == 0) g_vnorm[(size_t)it * G_TOT + g] = vnorm;

        // exp map, affine in (d, t)
        float ca = __cosf(vnorm);
        float k  = __fdividef(__sinf(vnorm), vnorm);
        float s2 = s * s;                       // = 1/t
        float cs = S1 * s2 * I32;               // c*s/32
        float P  = fmaf(-k, cs, ca * s);        // cos*s - k*cs
        float Q  = k * I32;
        d = fmaf(P, d, Q * gw);
        t = fmaxf(fmaf(P * P, t, fmaf(2.0f * P * Q, S1, Q * Q * S3)), 1e-24f);
        s = rsqrtf(t);
    }

    // ---- loss candidate t = 20 (never frozen)
    float dc = fminf(fmaxf(s * d, -1.0f + CLIPF), 1.0f - CLIPF);
    float th = acosf(dc);
    float ls = warpSum(th * th);
    if (lane == 0) g_lossT[(size_t)ITERS * G_TOT + g] = ls;
}

// ---------------------------------------------------------------------------
// Kernel 2: per-iteration max over groups of vnorm
// ---------------------------------------------------------------------------
__global__ void max_kernel() {
    __shared__ float sh[256];
    const int it = blockIdx.x;
    float m = 0.f;
    for (int i = threadIdx.x; i < G_TOT; i += 256)
        m = fmaxf(m, g_vnorm[(size_t)it * G_TOT + i]);
    sh[threadIdx.x] = m;
    __syncthreads();
    for (int s = 128; s > 0; s >>= 1) {
        if (threadIdx.x < s) sh[threadIdx.x] = fmaxf(sh[threadIdx.x], sh[threadIdx.x + s]);
        __syncthreads();
    }
    if (threadIdx.x == 0) g_maxv[it] = sh[0];
}

// ---------------------------------------------------------------------------
// Kernel 3: t* selection + deterministic mean of the selected losses
// ---------------------------------------------------------------------------
__global__ void final_kernel(float* __restrict__ out) {
    __shared__ float sh[1024];
    __shared__ int ts;
    if (threadIdx.x == 0) {
        int t = ITERS;
        for (int i = 0; i < ITERS; i++)
            if (g_maxv[i] < TOLF) { t = i; break; }
        ts = t;
    }
    __syncthreads();
    const int t = ts;
    float acc = 0.f;
    for (int i = threadIdx.x; i < G_TOT; i += 1024)
        acc += g_lossT[(size_t)t * G_TOT + i];
    sh[threadIdx.x] = acc;
    __syncthreads();
    for (int s = 512; s > 0; s >>= 1) {
        if (threadIdx.x < s) sh[threadIdx.x] += sh[threadIdx.x + s];
        __syncthreads();
    }
    if (threadIdx.x == 0) out[0] = sh[0] * (1.0f / (float)G_TOT);
}

// ---------------------------------------------------------------------------
extern "C" void kernel_launch(void* const* d_in, const int* in_sizes, int n_in,
                              void* d_out, int out_size) {
    const float* X = (const float*)d_in[0];
    float* out = (float*)d_out;

    karcher_kernel<<<G_TOT, 32>>>(X);
    max_kernel<<<ITERS, 256>>>();
    final_kernel<<<1, 1024>>>(out);
}

// round 14
// speedup vs baseline: 1.1776x; 1.0473x over previous
#include <cuda_runtime.h>
#include <cuda_bf16.h>
#include <math.h>

// Problem constants: NC=1000, K=8, N=32, D=128  -> G = 8000 groups
#define G_TOT 8000
#define NPT   32
#define DIM   128
#define ITERS 20
#define TOLF  1e-6f
#define EPSF  1e-7f
#define CLIPF 1e-7f

#define PN 34        // u64 pitch for k-pair-major chunk buffer
#define CT 33        // float pitch for Ct redistribution buffer

// Static scratch (no runtime allocation)
__device__ float g_vnorm[(size_t)ITERS * G_TOT];
__device__ float g_lossT[(size_t)(ITERS + 1) * G_TOT];
__device__ float g_maxv[ITERS];

using u64 = unsigned long long;

// ---- packed f32x2 helpers ----
__device__ __forceinline__ u64 pk2(float a, float b) {
    u64 r; asm("mov.b64 %0, {%1,%2};" : "=l"(r) : "f"(a), "f"(b)); return r;
}
__device__ __forceinline__ float2 upk2(u64 v) {
    float2 r; asm("mov.b64 {%0,%1}, %2;" : "=f"(r.x), "=f"(r.y) : "l"(v)); return r;
}
__device__ __forceinline__ u64 ffma2(u64 a, u64 b, u64 c) {
    u64 d; asm("fma.rn.f32x2 %0, %1, %2, %3;" : "=l"(d) : "l"(a), "l"(b), "l"(c)); return d;
}
__device__ __forceinline__ u64 fadd2(u64 a, u64 b) {
    u64 d; asm("add.rn.f32x2 %0, %1, %2;" : "=l"(d) : "l"(a), "l"(b)); return d;
}

__device__ __forceinline__ float warpSum(float v) {
    #pragma unroll
    for (int o = 16; o > 0; o >>= 1)
        v += __shfl_xor_sync(0xffffffffu, v, o);
    return v;
}

// ---------------------------------------------------------------------------
// Gram-space Karcher kernel, v4: matvec off the shuffle network.
// Per lane n: Gram row as 16 packed f32x2 (gp), d_n = (Ghat·alpha)_n.
// Warp scalars: t = alpha^T Ghat alpha, s = rsqrt(t). Exp map affine in (d,t).
// Matvec: w -> smem (double-buffered, 1 STS + 1 syncwarp), 8 broadcast
// LDS.128 reads of all 32 w's, 16 FFMA2. One 3-wide butterfly per iter.
// ---------------------------------------------------------------------------
__global__ void __launch_bounds__(32, 16) karcher_kernel(const float* __restrict__ X) {
    __shared__ u64   Xc2[16 * PN];                 // one 32-dim chunk, k-pair-major
    __shared__ float Ct[NPT * CT];                 // Gram redistribution buffer
    __shared__ float dsh[NPT];                     // diagonal (||x_n||^2)
    __shared__ float ish[NPT];                     // inv norms
    __shared__ __align__(16) float wbuf[2][NPT];   // double-buffered w line

    const int g    = blockIdx.x;
    const int lane = threadIdx.x;
    const int lr   = lane >> 2;         // row-block: rows 4lr..4lr+3
    const int lc   = lane & 3;          // col-block: cols 8lc..8lc+7
    const float4* __restrict__ Xg = (const float4*)X + (size_t)g * (NPT * DIM / 4);

    u64 acc[4][8];
    #pragma unroll
    for (int i = 0; i < 4; i++)
        #pragma unroll
        for (int j = 0; j < 8; j++) acc[i][j] = 0ull;

    // ---- Phase 1: streamed register-tiled Gram build (validated R11/R13)
    #pragma unroll 1
    for (int c = 0; c < 4; c++) {
        #pragma unroll
        for (int t = 0; t < 8; t++) {
            int p = 4 * t + (lane >> 3);
            int j = lane & 7;
            float4 v = Xg[p * 32 + c * 8 + j];
            Xc2[(2 * j)     * PN + p] = pk2(v.x, v.y);
            Xc2[(2 * j + 1) * PN + p] = pk2(v.z, v.w);
        }
        __syncwarp();

        #pragma unroll
        for (int k2 = 0; k2 < 16; k2++) {
            const u64* base = &Xc2[k2 * PN];
            u64 ar[4], bc[8];
            #pragma unroll
            for (int i = 0; i < 4; i++) ar[i] = base[4 * lr + i];
            #pragma unroll
            for (int j = 0; j < 8; j++) bc[j] = base[8 * lc + j];
            #pragma unroll
            for (int i = 0; i < 4; i++)
                #pragma unroll
                for (int j = 0; j < 8; j++)
                    acc[i][j] = ffma2(ar[i], bc[j], acc[i][j]);
        }
        __syncwarp();
    }

    float C[4][8];
    #pragma unroll
    for (int i = 0; i < 4; i++)
        #pragma unroll
        for (int j = 0; j < 8; j++) {
            float2 a = upk2(acc[i][j]);
            C[i][j] = a.x + a.y;
        }

    // ---- Phase 2: normalize + redistribute row-per-lane (packed pairs)
    #pragma unroll
    for (int i = 0; i < 4; i++) {
        int r = 4 * lr + i;
        if ((r >> 3) == lc) dsh[r] = C[i][r - 8 * lc];
    }
    __syncwarp();
    ish[lane] = rsqrtf(fmaxf(dsh[lane], 1e-24f));   // == 1/max(||x||,1e-12)
    __syncwarp();

    float ir[4], ic[8];
    #pragma unroll
    for (int i = 0; i < 4; i++) ir[i] = ish[4 * lr + i];
    #pragma unroll
    for (int j = 0; j < 8; j++) ic[j] = ish[8 * lc + j];
    #pragma unroll
    for (int i = 0; i < 4; i++)
        #pragma unroll
        for (int j = 0; j < 8; j++)
            Ct[(4 * lr + i) * CT + 8 * lc + j] = C[i][j] * ir[i] * ic[j];
    __syncwarp();

    // Gram row as 16 packed f32x2; LDS.32 pattern (lane*33 + 2j) is conflict-free
    u64 gp[16];
    #pragma unroll
    for (int j = 0; j < 16; j++)
        gp[j] = pk2(Ct[lane * CT + 2 * j], Ct[lane * CT + 2 * j + 1]);

    // ---- Phase 3: iteration (one butterfly, smem-broadcast matvec)
    float d;
    {
        u64 sum = 0ull;
        #pragma unroll
        for (int j = 0; j < 16; j++) sum = fadd2(sum, gp[j]);
        float2 sf = upk2(sum);
        d = sf.x + sf.y;                         // (Ghat·1)_lane
    }
    float t = fmaxf(warpSum(d), 1e-24f);         // alpha^T Ghat alpha
    float s = rsqrtf(t);                         // 1/||m^||

    const float I32   = 1.0f / 32.0f;
    const float I1024 = 1.0f / 1024.0f;

    #pragma unroll 1
    for (int it = 0; it < ITERS; ++it) {
        float dot   = s * d;
        float dc    = fminf(fmaxf(dot, -1.0f + CLIPF), 1.0f - CLIPF);
        float theta = acosf(dc);
        float st    = fmaxf(sqrtf(fmaf(-dc, dc, 1.0f)), EPSF);  // sin(acos(dc))
        float w     = __fdividef(theta, st);

        // ---- matvec gw = (Ghat·w)_lane via smem broadcast of w
        wbuf[it & 1][lane] = w;
        __syncwarp();      // also fences reads of slot (it&1) from iter it-2
        const float4* wb4 = (const float4*)wbuf[it & 1];
        u64 a0 = 0ull, a1 = 0ull;
        #pragma unroll
        for (int j = 0; j < 8; j++) {
            float4 q = wb4[j];                    // broadcast LDS.128
            a0 = ffma2(gp[2 * j],     pk2(q.x, q.y), a0);
            a1 = ffma2(gp[2 * j + 1], pk2(q.z, q.w), a1);
        }
        u64 asum = fadd2(a0, a1);
        float2 af = upk2(asum);
        float gw = af.x + af.y;

        // ---- ONE 3-wide butterfly: S1 = sum w*d, S2 = sum theta^2, S3 = sum w*gw
        u64   p1 = pk2(w * d, theta * theta);
        float p2 = w * gw;
        #pragma unroll
        for (int o = 16; o > 0; o >>= 1) {
            p1 = fadd2(p1, __shfl_xor_sync(0xffffffffu, p1, o));
            p2 +=          __shfl_xor_sync(0xffffffffu, p2, o);
        }
        float2 s12 = upk2(p1);
        float S1 = s12.x, S2 = s12.y, S3 = p2;
        if (lane == 0) g_lossT[(size_t)it * G_TOT + g] = S2;

        // ||v||^2 = (S3 - S1^2/t) / 1024
        float vq    = fmaxf((S3 - S1 * S1 * __fdividef(1.0f, t)) * I1024, 0.0f);
        float vnorm = fmaxf(sqrtf(vq), EPSF);
        if (lane == 0) g_vnorm[(size_t)it * G_TOT + g] = vnorm;

        // exp map, affine in (d, t)
        float ca = __cosf(vnorm);
        float k  = __fdividef(__sinf(vnorm), vnorm);
        float s2 = s * s;                       // = 1/t
        float cs = S1 * s2 * I32;               // c*s/32
        float P  = fmaf(-k, cs, ca * s);        // cos*s - k*cs
        float Q  = k * I32;
        d = fmaf(P, d, Q * gw);
        t = fmaxf(fmaf(P * P, t, fmaf(2.0f * P * Q, S1, Q * Q * S3)), 1e-24f);
        s = rsqrtf(t);
    }

    // ---- loss candidate t = 20 (never frozen)
    float dc = fminf(fmaxf(s * d, -1.0f + CLIPF), 1.0f - CLIPF);
    float th = acosf(dc);
    float ls = warpSum(th * th);
    if (lane == 0) g_lossT[(size_t)ITERS * G_TOT + g] = ls;
}

// ---------------------------------------------------------------------------
// Kernel 2: per-iteration max over groups of vnorm
// ---------------------------------------------------------------------------
__global__ void max_kernel() {
    __shared__ float sh[256];
    const int it = blockIdx.x;
    float m = 0.f;
    for (int i = threadIdx.x; i < G_TOT; i += 256)
        m = fmaxf(m, g_vnorm[(size_t)it * G_TOT + i]);
    sh[threadIdx.x] = m;
    __syncthreads();
    for (int s = 128; s > 0; s >>= 1) {
        if (threadIdx.x < s) sh[threadIdx.x] = fmaxf(sh[threadIdx.x], sh[threadIdx.x + s]);
        __syncthreads();
    }
    if (threadIdx.x == 0) g_maxv[it] = sh[0];
}

// ---------------------------------------------------------------------------
// Kernel 3: t* selection + deterministic mean of the selected losses
// ---------------------------------------------------------------------------
__global__ void final_kernel(float* __restrict__ out) {
    __shared__ float sh[1024];
    __shared__ int ts;
    if (threadIdx.x == 0) {
        int t = ITERS;
        for (int i = 0; i < ITERS; i++)
            if (g_maxv[i] < TOLF) { t = i; break; }
        ts = t;
    }
    __syncthreads();
    const int t = ts;
    float acc = 0.f;
    for (int i = threadIdx.x; i < G_TOT; i += 1024)
        acc += g_lossT[(size_t)t * G_TOT + i];
    sh[threadIdx.x] = acc;
    __syncthreads();
    for (int s = 512; s > 0; s >>= 1) {
        if (threadIdx.x < s) sh[threadIdx.x] += sh[threadIdx.x + s];
        __syncthreads();
    }
    if (threadIdx.x == 0) out[0] = sh[0] * (1.0f / (float)G_TOT);
}

// ---------------------------------------------------------------------------
extern "C" void kernel_launch(void* const* d_in, const int* in_sizes, int n_in,
                              void* d_out, int out_size) {
    const float* X = (const float*)d_in[0];
    float* out = (float*)d_out;

    karcher_kernel<<<G_TOT, 32>>>(X);
    max_kernel<<<ITERS, 256>>>();
    final_kernel<<<1, 1024>>>(out);
}